// round 11
// baseline (speedup 1.0000x reference)
#include <cuda_runtime.h>
#include <cuda_fp16.h>
#include <mma.h>
#include <cstdint>

using namespace nvcuda;

// ---------------------------------------------------------------------------
// GraphSAGE 2-layer forward, fp16 datapath:
//   warp-per-node CSR gathers (edges spread across lane groups, shfl-reduce),
//   wmma fp16 GEMM with fp32 accumulate + fp16 weight split (W = Wh + Wl).
// N = 100000, E = 1e6, d_in=64, d_hid=128, d_out=64.
// ---------------------------------------------------------------------------

#define N_NODES 100000
#define E_MAX   1000000
#define D_IN    64
#define D_HID   128
#define D_OUT   64

// Scratch (device globals; no allocation allowed)
__device__ int    g_cnt   [N_NODES];
__device__ int    g_rowptr[N_NODES + 1];
__device__ int    g_cursor[N_NODES];
__device__ int    g_csrsrc[E_MAX];
__device__ __half g_xh    [N_NODES * D_IN];    // fp16 mirror of x
__device__ __half g_h1h   [N_NODES * D_HID];   // fp16 h1 (sole copy)
__device__ __half g_agg1h [N_NODES * D_IN];    // fp16 mean-agg for layer 1
__device__ __half g_agg2h [N_NODES * D_HID];   // fp16 mean-agg for layer 2
__device__ __half g_B1h[128 * 128];            // [K][N] hi(W1) fp16
__device__ __half g_B1l[128 * 128];            // lo(W1)
__device__ __half g_B2h[256 * 64];             // [K][N] hi(W2)
__device__ __half g_B2l[256 * 64];             // lo(W2)

// ===========================================================================
// CSR build
// ===========================================================================
__global__ void zero_int_kernel(int4* __restrict__ p, int n4) {
    int i = blockIdx.x * blockDim.x + threadIdx.x;
    if (i < n4) p[i] = make_int4(0, 0, 0, 0);
}

__global__ void count_kernel(const int2* __restrict__ dst2, int* __restrict__ cnt, int E2) {
    int e = blockIdx.x * blockDim.x + threadIdx.x;
    if (e < E2) {
        int2 d = dst2[e];
        atomicAdd(&cnt[d.x], 1);
        atomicAdd(&cnt[d.y], 1);
    }
}

__global__ __launch_bounds__(1024)
void scan_kernel(const int* __restrict__ cnt,
                 int* __restrict__ row_ptr,
                 int* __restrict__ cursor, int n) {
    __shared__ int sums[1024];
    const int tid = threadIdx.x;
    const int chunk = (n + 1023) / 1024;
    const int begin = tid * chunk;
    const int end = min(begin + chunk, n);
    int s = 0;
    for (int i = begin; i < end; i++) s += cnt[i];
    sums[tid] = s;
    __syncthreads();
    for (int off = 1; off < 1024; off <<= 1) {
        int v = 0;
        if (tid >= off) v = sums[tid - off];
        __syncthreads();
        if (tid >= off) sums[tid] += v;
        __syncthreads();
    }
    int prefix = (tid == 0) ? 0 : sums[tid - 1];
    for (int i = begin; i < end; i++) {
        row_ptr[i] = prefix;
        cursor[i] = prefix;
        prefix += cnt[i];
    }
    if (tid == 1023) row_ptr[n] = sums[1023];
}

__global__ void fill_kernel(const int2* __restrict__ src2,
                            const int2* __restrict__ dst2,
                            int* __restrict__ cursor,
                            int* __restrict__ csr, int E2) {
    int e = blockIdx.x * blockDim.x + threadIdx.x;
    if (e < E2) {
        int2 s = src2[e];
        int2 d = dst2[e];
        int p0 = atomicAdd(&cursor[d.x], 1);
        csr[p0] = s.x;
        int p1 = atomicAdd(&cursor[d.y], 1);
        csr[p1] = s.y;
    }
}

// fp32 -> fp16 mirror
__global__ void f2h_kernel(const float4* __restrict__ in,
                           __half2* __restrict__ out, int n4) {
    int i = blockIdx.x * blockDim.x + threadIdx.x;
    if (i >= n4) return;
    float4 v = in[i];
    out[i * 2]     = __floats2half2_rn(v.x, v.y);
    out[i * 2 + 1] = __floats2half2_rn(v.z, v.w);
}

// ===========================================================================
// Warp-per-node gather + mean over fp16 features.
// NCOL uint4 columns per feature row; EPW = 32/NCOL edges in flight per
// iteration (lane = edge_slot*NCOL + col). fp32 accumulation, shfl_xor
// reduction across edge slots, lanes of slot 0 write the fp16 mean.
// ===========================================================================
template <int NCOL>
__global__ __launch_bounds__(256)
void gather_w_kernel(const uint4* __restrict__ feat,
                     const int* __restrict__ csr,
                     const int* __restrict__ row_ptr,
                     uint4* __restrict__ aggmean_h, int n) {
    constexpr int EPW = 32 / NCOL;          // edge slots per warp
    const int warp = threadIdx.x >> 5;
    const int lane = threadIdx.x & 31;
    const int c = lane % NCOL;              // uint4 column
    const int g = lane / NCOL;              // edge slot
    const int node = blockIdx.x * 8 + warp;
    if (node >= n) return;

    const int b = row_ptr[node];
    const int e = row_ptr[node + 1];
    float acc[8];
#pragma unroll
    for (int q = 0; q < 8; q++) acc[q] = 0.f;

    for (int i = b + g; i < e; i += EPW) {
        int s = __ldg(&csr[i]);
        uint4 r = __ldg(&feat[(size_t)s * NCOL + c]);
        const __half2* ph = reinterpret_cast<const __half2*>(&r);
#pragma unroll
        for (int q = 0; q < 4; q++) {
            float2 f = __half22float2(ph[q]);
            acc[2 * q]     += f.x;
            acc[2 * q + 1] += f.y;
        }
    }

    // reduce across edge slots (lanes with the same column index)
#pragma unroll
    for (int off = NCOL; off < 32; off <<= 1) {
#pragma unroll
        for (int q = 0; q < 8; q++)
            acc[q] += __shfl_xor_sync(0xFFFFFFFFu, acc[q], off);
    }

    if (g == 0) {
        int d = e - b;
        float inv = 1.0f / (float)(d > 1 ? d : 1);
        __half2 h0 = __floats2half2_rn(acc[0] * inv, acc[1] * inv);
        __half2 h1 = __floats2half2_rn(acc[2] * inv, acc[3] * inv);
        __half2 h2 = __floats2half2_rn(acc[4] * inv, acc[5] * inv);
        __half2 h3 = __floats2half2_rn(acc[6] * inv, acc[7] * inv);
        aggmean_h[(size_t)node * NCOL + c] = make_uint4(
            *(uint32_t*)&h0, *(uint32_t*)&h1, *(uint32_t*)&h2, *(uint32_t*)&h3);
    }
}

// ===========================================================================
// Weight prep: W = [Ws; Wn] stacked -> fp16 hi/lo split, row-major [DK2][NOUT]
// ===========================================================================
template <int DK2, int NOUT>
__global__ void wprep_kernel(const float* __restrict__ ws,
                             const float* __restrict__ wn,
                             __half* __restrict__ Bh,
                             __half* __restrict__ Bl) {
    int i = blockIdx.x * blockDim.x + threadIdx.x;
    if (i >= DK2 * NOUT) return;
    int k = i / NOUT, n = i % NOUT;
    float w = (k < DK2 / 2) ? ws[k * NOUT + n] : wn[(k - DK2 / 2) * NOUT + n];
    __half hi = __float2half_rn(w);
    Bh[i] = hi;
    Bl[i] = __float2half_rn(w - __half2float(hi));
}

// ===========================================================================
// Layer via wmma fp16 GEMM with weight hi/lo compensation.
// CTA = 128 nodes x NOUT, 8 warps. Warp tile (WROWS*16) x (WCOLS*16).
// A chunks staged by straight fp16 copy (self mirror / fp16 agg).
// LAYER==1: self = xh,  agg = agg1h. Output: fp16 h1h.
// LAYER==2: self = h1h, agg = agg2h. Output: fp32 d_out.
// ===========================================================================
template <int NOUT, int WROWS, int WCOLS, int NCHUNK, int LAYER, bool RELU, bool HALF_OUT>
__global__ __launch_bounds__(256)
void wmma_layer_kernel(const __half* __restrict__ selfh,
                       const __half* __restrict__ aggh,
                       const __half* __restrict__ Bh,
                       const __half* __restrict__ Bl,
                       const float* __restrict__ bias,
                       float* __restrict__ out,
                       __half* __restrict__ outh, int nNodes) {
    constexpr int ROWU4 = (LAYER == 1) ? 8 : 16;  // fp16 source row in uint4
    constexpr int ASTR  = 72;                     // smem A row stride (halfs)
    constexpr int BSTR  = NOUT + 8;               // smem B row stride (halfs)
    constexpr int COLG  = NOUT / (WCOLS * 16);    // warp col groups

    extern __shared__ __align__(32) char smem_raw[];
    __half* sA  = (__half*)smem_raw;                 // 128 x ASTR
    __half* sBh = sA + 128 * ASTR;                   // 64 x BSTR
    __half* sBl = sBh + 64 * BSTR;                   // 64 x BSTR
    float*  sBias = (float*)(sBl + 64 * BSTR);       // 2048 floats

    const int tid = threadIdx.x;
    const int wid = tid >> 5;
    const int lane = tid & 31;
    const int rowg = wid / COLG;
    const int colg = wid % COLG;
    const int base = blockIdx.x * 128;

    for (int i = tid; i < 16 * NOUT; i += 256) sBias[i] = bias[i % NOUT];
    __syncthreads();

    wmma::fragment<wmma::accumulator, 16, 16, 16, float> acc[WROWS][WCOLS];
#pragma unroll
    for (int r = 0; r < WROWS; r++)
#pragma unroll
        for (int c = 0; c < WCOLS; c++)
            wmma::load_matrix_sync(acc[r][c],
                sBias + (colg * WCOLS + c) * 16, NOUT, wmma::mem_row_major);

    for (int kc = 0; kc < NCHUNK; kc++) {
        __syncthreads();

        // ---- stage A: straight fp16 copy, 128 rows x 64 cols ----
        const uint4* src4;
        int qoff;
        if (LAYER == 1) {
            src4 = reinterpret_cast<const uint4*>(kc ? aggh : selfh);
            qoff = 0;
        } else {
            src4 = reinterpret_cast<const uint4*>((kc < 2) ? selfh : aggh);
            qoff = (kc & 1) * 8;
        }
#pragma unroll
        for (int jj = tid; jj < 1024; jj += 256) {
            int m = jj >> 3, c8 = jj & 7;
            int node = base + m;
            uint4 v = make_uint4(0, 0, 0, 0);
            if (node < nNodes)
                v = src4[(size_t)node * ROWU4 + qoff + c8];
            *reinterpret_cast<uint4*>(&sA[m * ASTR + c8 * 8]) = v;
        }
        // ---- stage B: 64 x NOUT fp16 hi/lo ----
#pragma unroll
        for (int jj = tid; jj < 64 * NOUT / 8; jj += 256) {
            int r = jj / (NOUT / 8), c8 = jj % (NOUT / 8);
            size_t g = (size_t)(kc * 64 + r) * NOUT + c8 * 8;
            *reinterpret_cast<uint4*>(&sBh[r * BSTR + c8 * 8]) =
                *reinterpret_cast<const uint4*>(&Bh[g]);
            *reinterpret_cast<uint4*>(&sBl[r * BSTR + c8 * 8]) =
                *reinterpret_cast<const uint4*>(&Bl[g]);
        }
        __syncthreads();

        // ---- MMA over 4 k-steps of 16 ----
#pragma unroll
        for (int kk = 0; kk < 4; kk++) {
            wmma::fragment<wmma::matrix_a, 16, 16, 16, __half, wmma::row_major> a[WROWS];
#pragma unroll
            for (int r = 0; r < WROWS; r++) {
                int rr = (rowg * WROWS + r) * 16;
                wmma::load_matrix_sync(a[r], sA + rr * ASTR + kk * 16, ASTR);
            }
#pragma unroll
            for (int c = 0; c < WCOLS; c++) {
                wmma::fragment<wmma::matrix_b, 16, 16, 16, __half, wmma::row_major> bh, bl;
                int cc = (colg * WCOLS + c) * 16;
                wmma::load_matrix_sync(bh, sBh + kk * 16 * BSTR + cc, BSTR);
                wmma::load_matrix_sync(bl, sBl + kk * 16 * BSTR + cc, BSTR);
#pragma unroll
                for (int r = 0; r < WROWS; r++) {
                    wmma::mma_sync(acc[r][c], a[r], bh, acc[r][c]);
                    wmma::mma_sync(acc[r][c], a[r], bl, acc[r][c]);
                }
            }
        }
    }

    // ---- epilogue ----
    float* scratch = sBias + wid * 256;   // per-warp 16x16 fp32 tile
#pragma unroll
    for (int r = 0; r < WROWS; r++) {
        int rbase = base + (rowg * WROWS + r) * 16;
        if (rbase < nNodes) {
#pragma unroll
            for (int c = 0; c < WCOLS; c++) {
                if (RELU) {
#pragma unroll
                    for (int i = 0; i < acc[r][c].num_elements; i++)
                        acc[r][c].x[i] = fmaxf(acc[r][c].x[i], 0.f);
                }
                int cc = (colg * WCOLS + c) * 16;
                if (HALF_OUT) {
                    __syncwarp();
                    wmma::store_matrix_sync(scratch, acc[r][c], 16,
                                            wmma::mem_row_major);
                    __syncwarp();
                    int lr = lane >> 1, lc = (lane & 1) * 8;
                    float4 va = *reinterpret_cast<float4*>(&scratch[lr * 16 + lc]);
                    float4 vb = *reinterpret_cast<float4*>(&scratch[lr * 16 + lc + 4]);
                    __half2 h0 = __floats2half2_rn(va.x, va.y);
                    __half2 h1 = __floats2half2_rn(va.z, va.w);
                    __half2 h2 = __floats2half2_rn(vb.x, vb.y);
                    __half2 h3 = __floats2half2_rn(vb.z, vb.w);
                    uint4 packed = make_uint4(
                        *(uint32_t*)&h0, *(uint32_t*)&h1,
                        *(uint32_t*)&h2, *(uint32_t*)&h3);
                    *reinterpret_cast<uint4*>(
                        &outh[(size_t)(rbase + lr) * NOUT + cc + lc]) = packed;
                } else {
                    wmma::store_matrix_sync(
                        out + (size_t)rbase * NOUT + cc,
                        acc[r][c], NOUT, wmma::mem_row_major);
                }
            }
        }
    }
}

// ===========================================================================
extern "C" void kernel_launch(void* const* d_in, const int* in_sizes, int n_in,
                              void* d_out, int out_size) {
    const float* x        = (const float*)d_in[0];
    const int*   src      = (const int*)d_in[1];
    const int*   dst      = (const int*)d_in[2];
    const float* w_self1  = (const float*)d_in[3];
    const float* w_neigh1 = (const float*)d_in[4];
    const float* b1       = (const float*)d_in[5];
    const float* w_self2  = (const float*)d_in[6];
    const float* w_neigh2 = (const float*)d_in[7];
    const float* b2       = (const float*)d_in[8];
    float* out = (float*)d_out;

    const int E = in_sizes[1];

    int *cnt, *rowptr, *cursor, *csrsrc;
    __half *xh, *h1h, *agg1h, *agg2h;
    __half *B1h, *B1l, *B2h, *B2l;
    cudaGetSymbolAddress((void**)&cnt,    g_cnt);
    cudaGetSymbolAddress((void**)&rowptr, g_rowptr);
    cudaGetSymbolAddress((void**)&cursor, g_cursor);
    cudaGetSymbolAddress((void**)&csrsrc, g_csrsrc);
    cudaGetSymbolAddress((void**)&xh,     g_xh);
    cudaGetSymbolAddress((void**)&h1h,    g_h1h);
    cudaGetSymbolAddress((void**)&agg1h,  g_agg1h);
    cudaGetSymbolAddress((void**)&agg2h,  g_agg2h);
    cudaGetSymbolAddress((void**)&B1h,    g_B1h);
    cudaGetSymbolAddress((void**)&B1l,    g_B1l);
    cudaGetSymbolAddress((void**)&B2h,    g_B2h);
    cudaGetSymbolAddress((void**)&B2l,    g_B2l);

    // smem: A (128x72 half) + B hi/lo (2 x 64 x (NOUT+8) half) + 2048 floats
    constexpr int SMEM_L1 = 128 * 72 * 2 + 2 * 64 * (128 + 8) * 2 + 2048 * 4; // 61440
    constexpr int SMEM_L2 = 128 * 72 * 2 + 2 * 64 * (64 + 8) * 2 + 2048 * 4;  // 45056
    cudaFuncSetAttribute((const void*)wmma_layer_kernel<D_HID, 2, 4, 2, 1, true, true>,
                         cudaFuncAttributeMaxDynamicSharedMemorySize, SMEM_L1);
    cudaFuncSetAttribute((const void*)wmma_layer_kernel<D_OUT, 1, 4, 4, 2, false, false>,
                         cudaFuncAttributeMaxDynamicSharedMemorySize, SMEM_L2);

    const int nTiles = (N_NODES + 127) / 128;
    const int E2 = E / 2;   // E is even (1e6)

    // --- CSR build (launches 1-4) ---
    zero_int_kernel<<<(N_NODES / 4 + 255) / 256, 256>>>((int4*)cnt, N_NODES / 4);
    count_kernel<<<(E2 + 255) / 256, 256>>>((const int2*)dst, cnt, E2);
    scan_kernel<<<1, 1024>>>(cnt, rowptr, cursor, N_NODES);
    fill_kernel<<<(E2 + 255) / 256, 256>>>(
        (const int2*)src, (const int2*)dst, cursor, csrsrc, E2);

    // --- x fp16 mirror (launch 5) ---
    f2h_kernel<<<(N_NODES * D_IN / 4 + 255) / 256, 256>>>(
        (const float4*)x, (__half2*)xh, N_NODES * D_IN / 4);

    // --- gather 1 (launch 6 -> ncu capture target) ---
    gather_w_kernel<D_IN / 8><<<(N_NODES + 7) / 8, 256>>>(
        (const uint4*)xh, csrsrc, rowptr, (uint4*)agg1h, N_NODES);

    // --- weight prep (independent of gathers; before layer kernels) ---
    wprep_kernel<128, 128><<<(128 * 128 + 255) / 256, 256>>>(w_self1, w_neigh1, B1h, B1l);
    wprep_kernel<256, 64><<<(256 * 64 + 255) / 256, 256>>>(w_self2, w_neigh2, B2h, B2l);

    // --- Layer 1 ---
    wmma_layer_kernel<D_HID, 2, 4, 2, 1, true, true><<<nTiles, 256, SMEM_L1>>>(
        xh, agg1h, B1h, B1l, b1, nullptr, h1h, N_NODES);

    // --- Layer 2 ---
    gather_w_kernel<D_HID / 8><<<(N_NODES + 7) / 8, 256>>>(
        (const uint4*)h1h, csrsrc, rowptr, (uint4*)agg2h, N_NODES);
    wmma_layer_kernel<D_OUT, 1, 4, 4, 2, false, false><<<nTiles, 256, SMEM_L2>>>(
        h1h, agg2h, B2h, B2l, b2, out, nullptr, N_NODES);
}

// round 12
// speedup vs baseline: 1.0471x; 1.0471x over previous
#include <cuda_runtime.h>
#include <cuda_fp16.h>
#include <mma.h>
#include <cstdint>

using namespace nvcuda;

// ---------------------------------------------------------------------------
// GraphSAGE 2-layer forward, fp16 datapath:
//   per-node-group CSR gathers (HADD2 pair accumulation), wmma fp16 GEMM with
//   fp32 accumulate + fp16 weight split (W = Wh + Wl), cp.async double-
//   buffered staging pipeline in the layer kernels.
// N = 100000, E = 1e6, d_in=64, d_hid=128, d_out=64.
// ---------------------------------------------------------------------------

#define N_NODES 100000
#define E_MAX   1000000
#define D_IN    64
#define D_HID   128
#define D_OUT   64

// Scratch (device globals; no allocation allowed)
__device__ int    g_cnt   [N_NODES];
__device__ int    g_rowptr[N_NODES + 1];
__device__ int    g_cursor[N_NODES];
__device__ int    g_csrsrc[E_MAX];
__device__ __half g_xh    [N_NODES * D_IN];    // fp16 mirror of x
__device__ __half g_h1h   [N_NODES * D_HID];   // fp16 h1 (sole copy)
__device__ __half g_agg1h [N_NODES * D_IN];    // fp16 mean-agg for layer 1
__device__ __half g_agg2h [N_NODES * D_HID];   // fp16 mean-agg for layer 2
__device__ __half g_B1h[128 * 128];            // [K][N] hi(W1) fp16
__device__ __half g_B1l[128 * 128];            // lo(W1)
__device__ __half g_B2h[256 * 64];             // [K][N] hi(W2)
__device__ __half g_B2l[256 * 64];             // lo(W2)

// ---------------------------------------------------------------------------
__device__ __forceinline__ uint32_t smem_u32(const void* p) {
    return (uint32_t)__cvta_generic_to_shared(p);
}
// 16B cp.async with zero-fill when invalid
__device__ __forceinline__ void cp_async16(uint32_t dst, const void* src, bool valid) {
    int sz = valid ? 16 : 0;
    asm volatile("cp.async.cg.shared.global [%0], [%1], 16, %2;\n"
                 :: "r"(dst), "l"(src), "r"(sz) : "memory");
}
__device__ __forceinline__ void cp_commit() {
    asm volatile("cp.async.commit_group;\n" ::: "memory");
}
template <int N>
__device__ __forceinline__ void cp_wait() {
    asm volatile("cp.async.wait_group %0;\n" :: "n"(N) : "memory");
}

// ===========================================================================
// CSR build
// ===========================================================================
__global__ void zero_int_kernel(int4* __restrict__ p, int n4) {
    int i = blockIdx.x * blockDim.x + threadIdx.x;
    if (i < n4) p[i] = make_int4(0, 0, 0, 0);
}

__global__ void count_kernel(const int2* __restrict__ dst2, int* __restrict__ cnt, int E2) {
    int e = blockIdx.x * blockDim.x + threadIdx.x;
    if (e < E2) {
        int2 d = dst2[e];
        atomicAdd(&cnt[d.x], 1);
        atomicAdd(&cnt[d.y], 1);
    }
}

__global__ __launch_bounds__(1024)
void scan_kernel(const int* __restrict__ cnt,
                 int* __restrict__ row_ptr,
                 int* __restrict__ cursor, int n) {
    __shared__ int sums[1024];
    const int tid = threadIdx.x;
    const int chunk = (n + 1023) / 1024;
    const int begin = tid * chunk;
    const int end = min(begin + chunk, n);
    int s = 0;
    for (int i = begin; i < end; i++) s += cnt[i];
    sums[tid] = s;
    __syncthreads();
    for (int off = 1; off < 1024; off <<= 1) {
        int v = 0;
        if (tid >= off) v = sums[tid - off];
        __syncthreads();
        if (tid >= off) sums[tid] += v;
        __syncthreads();
    }
    int prefix = (tid == 0) ? 0 : sums[tid - 1];
    for (int i = begin; i < end; i++) {
        row_ptr[i] = prefix;
        cursor[i] = prefix;
        prefix += cnt[i];
    }
    if (tid == 1023) row_ptr[n] = sums[1023];
}

__global__ void fill_kernel(const int2* __restrict__ src2,
                            const int2* __restrict__ dst2,
                            int* __restrict__ cursor,
                            int* __restrict__ csr, int E2) {
    int e = blockIdx.x * blockDim.x + threadIdx.x;
    if (e < E2) {
        int2 s = src2[e];
        int2 d = dst2[e];
        int p0 = atomicAdd(&cursor[d.x], 1);
        csr[p0] = s.x;
        int p1 = atomicAdd(&cursor[d.y], 1);
        csr[p1] = s.y;
    }
}

// fp32 -> fp16 mirror
__global__ void f2h_kernel(const float4* __restrict__ in,
                           __half2* __restrict__ out, int n4) {
    int i = blockIdx.x * blockDim.x + threadIdx.x;
    if (i >= n4) return;
    float4 v = in[i];
    out[i * 2]     = __floats2half2_rn(v.x, v.y);
    out[i * 2 + 1] = __floats2half2_rn(v.z, v.w);
}

// ===========================================================================
// Gather + mean over fp16 features (R10 form). Edge pairs summed via HADD2,
// accumulated fp32. TPN threads per node; one LDG.128 per thread per edge.
// ===========================================================================
template <int TPN>
__global__ __launch_bounds__(256)
void gather_h_kernel(const uint4* __restrict__ feat,
                     const int* __restrict__ csr,
                     const int* __restrict__ row_ptr,
                     uint4* __restrict__ aggmean_h, int n) {
    const int tid = threadIdx.x;
    const int node = blockIdx.x * (256 / TPN) + tid / TPN;
    const int c = tid % TPN;
    if (node >= n) return;
    const int b = row_ptr[node];
    const int e = row_ptr[node + 1];
    float acc[8];
#pragma unroll
    for (int q = 0; q < 8; q++) acc[q] = 0.f;

    int i = b;
#pragma unroll 2
    for (; i + 1 < e; i += 2) {
        int s0 = __ldg(&csr[i]);
        int s1 = __ldg(&csr[i + 1]);
        uint4 r0 = __ldg(&feat[(size_t)s0 * TPN + c]);
        uint4 r1 = __ldg(&feat[(size_t)s1 * TPN + c]);
        const __half2* p0 = reinterpret_cast<const __half2*>(&r0);
        const __half2* p1 = reinterpret_cast<const __half2*>(&r1);
#pragma unroll
        for (int q = 0; q < 4; q++) {
            __half2 hs = __hadd2(p0[q], p1[q]);
            float2 f = __half22float2(hs);
            acc[2 * q]     += f.x;
            acc[2 * q + 1] += f.y;
        }
    }
    if (i < e) {
        int s = __ldg(&csr[i]);
        uint4 r = __ldg(&feat[(size_t)s * TPN + c]);
        const __half2* ph = reinterpret_cast<const __half2*>(&r);
#pragma unroll
        for (int q = 0; q < 4; q++) {
            float2 f = __half22float2(ph[q]);
            acc[2 * q]     += f.x;
            acc[2 * q + 1] += f.y;
        }
    }

    int d = e - b;
    float inv = 1.0f / (float)(d > 1 ? d : 1);
    __half2 h0 = __floats2half2_rn(acc[0] * inv, acc[1] * inv);
    __half2 h1 = __floats2half2_rn(acc[2] * inv, acc[3] * inv);
    __half2 h2 = __floats2half2_rn(acc[4] * inv, acc[5] * inv);
    __half2 h3 = __floats2half2_rn(acc[6] * inv, acc[7] * inv);
    aggmean_h[(size_t)node * TPN + c] = make_uint4(
        *(uint32_t*)&h0, *(uint32_t*)&h1, *(uint32_t*)&h2, *(uint32_t*)&h3);
}

// ===========================================================================
// Weight prep: W = [Ws; Wn] stacked -> fp16 hi/lo split, row-major [DK2][NOUT]
// ===========================================================================
template <int DK2, int NOUT>
__global__ void wprep_kernel(const float* __restrict__ ws,
                             const float* __restrict__ wn,
                             __half* __restrict__ Bh,
                             __half* __restrict__ Bl) {
    int i = blockIdx.x * blockDim.x + threadIdx.x;
    if (i >= DK2 * NOUT) return;
    int k = i / NOUT, n = i % NOUT;
    float w = (k < DK2 / 2) ? ws[k * NOUT + n] : wn[(k - DK2 / 2) * NOUT + n];
    __half hi = __float2half_rn(w);
    Bh[i] = hi;
    Bl[i] = __float2half_rn(w - __half2float(hi));
}

// ===========================================================================
// Layer via wmma fp16 GEMM, cp.async double-buffered staging pipeline.
// CTA = 128 nodes x NOUT, 8 warps. Warp tile (WROWS*16) x (WCOLS*16).
// LAYER==1: self = xh,  agg = agg1h. Output: fp16 h1h.
// LAYER==2: self = h1h, agg = agg2h. Output: fp32 d_out.
// ===========================================================================
template <int NOUT, int WROWS, int WCOLS, int NCHUNK, int LAYER, bool RELU, bool HALF_OUT>
__global__ __launch_bounds__(256)
void wmma_layer_kernel(const __half* __restrict__ selfh,
                       const __half* __restrict__ aggh,
                       const __half* __restrict__ Bh,
                       const __half* __restrict__ Bl,
                       const float* __restrict__ bias,
                       float* __restrict__ out,
                       __half* __restrict__ outh, int nNodes) {
    constexpr int ROWU4 = (LAYER == 1) ? 8 : 16;  // fp16 source row in uint4
    constexpr int ASTR  = 72;                     // smem A row stride (halfs)
    constexpr int BSTR  = NOUT + 8;               // smem B row stride (halfs)
    constexpr int COLG  = NOUT / (WCOLS * 16);    // warp col groups
    constexpr int ABUF  = 128 * ASTR;             // halfs per A buffer
    constexpr int BBUF  = 64 * BSTR;              // halfs per B buffer

    extern __shared__ __align__(32) char smem_raw[];
    __half* sA  = (__half*)smem_raw;                 // 2 x ABUF
    __half* sBh = sA + 2 * ABUF;                     // 2 x BBUF
    __half* sBl = sBh + 2 * BBUF;                    // 2 x BBUF
    float*  sBias = (float*)(sBl + 2 * BBUF);        // 2048 floats

    const int tid = threadIdx.x;
    const int wid = tid >> 5;
    const int lane = tid & 31;
    const int rowg = wid / COLG;
    const int colg = wid % COLG;
    const int base = blockIdx.x * 128;

    // ---- stage issue helper (cp.async, one commit per chunk) ----
    auto stage = [&](int kc) {
        const int buf = kc & 1;
        const uint4* src4;
        int qoff;
        if (LAYER == 1) {
            src4 = reinterpret_cast<const uint4*>(kc ? aggh : selfh);
            qoff = 0;
        } else {
            src4 = reinterpret_cast<const uint4*>((kc < 2) ? selfh : aggh);
            qoff = (kc & 1) * 8;
        }
        // A: 128 rows x 8 uint4
#pragma unroll
        for (int jj = tid; jj < 1024; jj += 256) {
            int m = jj >> 3, c8 = jj & 7;
            int node = base + m;
            uint32_t dst = smem_u32(&sA[buf * ABUF + m * ASTR + c8 * 8]);
            cp_async16(dst, src4 + (size_t)node * ROWU4 + qoff + c8,
                       node < nNodes);
        }
        // B hi/lo: 64 rows x NOUT/8 uint4 each
#pragma unroll
        for (int jj = tid; jj < 64 * NOUT / 8; jj += 256) {
            int r = jj / (NOUT / 8), c8 = jj % (NOUT / 8);
            size_t g = (size_t)(kc * 64 + r) * NOUT + c8 * 8;
            cp_async16(smem_u32(&sBh[buf * BBUF + r * BSTR + c8 * 8]), Bh + g, true);
            cp_async16(smem_u32(&sBl[buf * BBUF + r * BSTR + c8 * 8]), Bl + g, true);
        }
        cp_commit();
    };

    for (int i = tid; i < 16 * NOUT; i += 256) sBias[i] = bias[i % NOUT];

    wmma::fragment<wmma::accumulator, 16, 16, 16, float> acc[WROWS][WCOLS];

    // prologue: issue chunk 0, init accumulators from bias while it lands
    stage(0);
    __syncthreads();   // sBias ready
#pragma unroll
    for (int r = 0; r < WROWS; r++)
#pragma unroll
        for (int c = 0; c < WCOLS; c++)
            wmma::load_matrix_sync(acc[r][c],
                sBias + (colg * WCOLS + c) * 16, NOUT, wmma::mem_row_major);

    for (int kc = 0; kc < NCHUNK; kc++) {
        const int buf = kc & 1;
        if (kc + 1 < NCHUNK) {
            stage(kc + 1);
            cp_wait<1>();   // chunk kc complete
        } else {
            cp_wait<0>();
        }
        __syncthreads();

        // ---- MMA over 4 k-steps of 16 ----
#pragma unroll
        for (int kk = 0; kk < 4; kk++) {
            wmma::fragment<wmma::matrix_a, 16, 16, 16, __half, wmma::row_major> a[WROWS];
#pragma unroll
            for (int r = 0; r < WROWS; r++) {
                int rr = (rowg * WROWS + r) * 16;
                wmma::load_matrix_sync(a[r], sA + buf * ABUF + rr * ASTR + kk * 16, ASTR);
            }
#pragma unroll
            for (int c = 0; c < WCOLS; c++) {
                wmma::fragment<wmma::matrix_b, 16, 16, 16, __half, wmma::row_major> bh, bl;
                int cc = (colg * WCOLS + c) * 16;
                wmma::load_matrix_sync(bh, sBh + buf * BBUF + kk * 16 * BSTR + cc, BSTR);
                wmma::load_matrix_sync(bl, sBl + buf * BBUF + kk * 16 * BSTR + cc, BSTR);
#pragma unroll
                for (int r = 0; r < WROWS; r++) {
                    wmma::mma_sync(acc[r][c], a[r], bh, acc[r][c]);
                    wmma::mma_sync(acc[r][c], a[r], bl, acc[r][c]);
                }
            }
        }
        __syncthreads();   // all warps done with buf before it is re-staged
    }

    // ---- epilogue ----
    float* scratch = sBias + wid * 256;   // per-warp 16x16 fp32 tile
#pragma unroll
    for (int r = 0; r < WROWS; r++) {
        int rbase = base + (rowg * WROWS + r) * 16;
        if (rbase < nNodes) {
#pragma unroll
            for (int c = 0; c < WCOLS; c++) {
                if (RELU) {
#pragma unroll
                    for (int i = 0; i < acc[r][c].num_elements; i++)
                        acc[r][c].x[i] = fmaxf(acc[r][c].x[i], 0.f);
                }
                int cc = (colg * WCOLS + c) * 16;
                if (HALF_OUT) {
                    __syncwarp();
                    wmma::store_matrix_sync(scratch, acc[r][c], 16,
                                            wmma::mem_row_major);
                    __syncwarp();
                    int lr = lane >> 1, lc = (lane & 1) * 8;
                    float4 va = *reinterpret_cast<float4*>(&scratch[lr * 16 + lc]);
                    float4 vb = *reinterpret_cast<float4*>(&scratch[lr * 16 + lc + 4]);
                    __half2 h0 = __floats2half2_rn(va.x, va.y);
                    __half2 h1 = __floats2half2_rn(va.z, va.w);
                    __half2 h2 = __floats2half2_rn(vb.x, vb.y);
                    __half2 h3 = __floats2half2_rn(vb.z, vb.w);
                    uint4 packed = make_uint4(
                        *(uint32_t*)&h0, *(uint32_t*)&h1,
                        *(uint32_t*)&h2, *(uint32_t*)&h3);
                    *reinterpret_cast<uint4*>(
                        &outh[(size_t)(rbase + lr) * NOUT + cc + lc]) = packed;
                } else {
                    wmma::store_matrix_sync(
                        out + (size_t)rbase * NOUT + cc,
                        acc[r][c], NOUT, wmma::mem_row_major);
                }
            }
        }
    }
}

// ===========================================================================
extern "C" void kernel_launch(void* const* d_in, const int* in_sizes, int n_in,
                              void* d_out, int out_size) {
    const float* x        = (const float*)d_in[0];
    const int*   src      = (const int*)d_in[1];
    const int*   dst      = (const int*)d_in[2];
    const float* w_self1  = (const float*)d_in[3];
    const float* w_neigh1 = (const float*)d_in[4];
    const float* b1       = (const float*)d_in[5];
    const float* w_self2  = (const float*)d_in[6];
    const float* w_neigh2 = (const float*)d_in[7];
    const float* b2       = (const float*)d_in[8];
    float* out = (float*)d_out;

    const int E = in_sizes[1];

    int *cnt, *rowptr, *cursor, *csrsrc;
    __half *xh, *h1h, *agg1h, *agg2h;
    __half *B1h, *B1l, *B2h, *B2l;
    cudaGetSymbolAddress((void**)&cnt,    g_cnt);
    cudaGetSymbolAddress((void**)&rowptr, g_rowptr);
    cudaGetSymbolAddress((void**)&cursor, g_cursor);
    cudaGetSymbolAddress((void**)&csrsrc, g_csrsrc);
    cudaGetSymbolAddress((void**)&xh,     g_xh);
    cudaGetSymbolAddress((void**)&h1h,    g_h1h);
    cudaGetSymbolAddress((void**)&agg1h,  g_agg1h);
    cudaGetSymbolAddress((void**)&agg2h,  g_agg2h);
    cudaGetSymbolAddress((void**)&B1h,    g_B1h);
    cudaGetSymbolAddress((void**)&B1l,    g_B1l);
    cudaGetSymbolAddress((void**)&B2h,    g_B2h);
    cudaGetSymbolAddress((void**)&B2l,    g_B2l);

    // smem: A 2x(128x72) + B 4x(64x(NOUT+8)) halfs + 2048 floats
    constexpr int SMEM_L1 = (2 * 128 * 72 + 4 * 64 * (128 + 8)) * 2 + 2048 * 4; // 114688
    constexpr int SMEM_L2 = (2 * 128 * 72 + 4 * 64 * (64 + 8)) * 2 + 2048 * 4;  // 81920
    cudaFuncSetAttribute((const void*)wmma_layer_kernel<D_HID, 2, 4, 2, 1, true, true>,
                         cudaFuncAttributeMaxDynamicSharedMemorySize, SMEM_L1);
    cudaFuncSetAttribute((const void*)wmma_layer_kernel<D_OUT, 1, 4, 4, 2, false, false>,
                         cudaFuncAttributeMaxDynamicSharedMemorySize, SMEM_L2);

    const int nTiles = (N_NODES + 127) / 128;
    const int E2 = E / 2;   // E is even (1e6)

    // launch 1: f2h (independent) -> shifts scan into the captured slot (#4)
    f2h_kernel<<<(N_NODES * D_IN / 4 + 255) / 256, 256>>>(
        (const float4*)x, (__half2*)xh, N_NODES * D_IN / 4);

    // --- CSR build (launches 2-5; scan is launch 4 -> ncu capture) ---
    zero_int_kernel<<<(N_NODES / 4 + 255) / 256, 256>>>((int4*)cnt, N_NODES / 4);
    count_kernel<<<(E2 + 255) / 256, 256>>>((const int2*)dst, cnt, E2);
    scan_kernel<<<1, 1024>>>(cnt, rowptr, cursor, N_NODES);
    fill_kernel<<<(E2 + 255) / 256, 256>>>(
        (const int2*)src, (const int2*)dst, cursor, csrsrc, E2);

    // --- weight prep ---
    wprep_kernel<128, 128><<<(128 * 128 + 255) / 256, 256>>>(w_self1, w_neigh1, B1h, B1l);
    wprep_kernel<256, 64><<<(256 * 64 + 255) / 256, 256>>>(w_self2, w_neigh2, B2h, B2l);

    // --- Layer 1 ---
    gather_h_kernel<D_IN / 8><<<(N_NODES * (D_IN / 8) + 255) / 256, 256>>>(
        (const uint4*)xh, csrsrc, rowptr, (uint4*)agg1h, N_NODES);
    wmma_layer_kernel<D_HID, 2, 4, 2, 1, true, true><<<nTiles, 256, SMEM_L1>>>(
        xh, agg1h, B1h, B1l, b1, nullptr, h1h, N_NODES);

    // --- Layer 2 ---
    gather_h_kernel<D_HID / 8><<<(N_NODES * (D_HID / 8) + 255) / 256, 256>>>(
        (const uint4*)h1h, csrsrc, rowptr, (uint4*)agg2h, N_NODES);
    wmma_layer_kernel<D_OUT, 1, 4, 4, 2, false, false><<<nTiles, 256, SMEM_L2>>>(
        h1h, agg2h, B2h, B2l, b2, out, nullptr, N_NODES);
}

// round 13
// speedup vs baseline: 2.0946x; 2.0004x over previous
#include <cuda_runtime.h>
#include <cuda_fp16.h>
#include <mma.h>
#include <cstdint>

using namespace nvcuda;

// ---------------------------------------------------------------------------
// GraphSAGE 2-layer forward, fp16 datapath:
//   CSR build with PARALLEL 3-phase scan (old single-block scan was 155us —
//   half the runtime), HADD2 pair-accumulating gathers, wmma fp16 GEMM with
//   fp32 accumulate + fp16 weight split (W = Wh + Wl).
// N = 100000, E = 1e6, d_in=64, d_hid=128, d_out=64.
// ---------------------------------------------------------------------------

#define N_NODES 100000
#define E_MAX   1000000
#define D_IN    64
#define D_HID   128
#define D_OUT   64
#define SCAN_TILE 1024
#define N_TILES ((N_NODES + SCAN_TILE - 1) / SCAN_TILE)   // 98

// Scratch (device globals; no allocation allowed)
__device__ int    g_cnt   [N_NODES];
__device__ int    g_rowptr[N_NODES + 1];
__device__ int    g_cursor[N_NODES];
__device__ int    g_bsum  [128];
__device__ int    g_csrsrc[E_MAX];
__device__ __half g_xh    [N_NODES * D_IN];    // fp16 mirror of x
__device__ __half g_h1h   [N_NODES * D_HID];   // fp16 h1 (sole copy)
__device__ __half g_agg1h [N_NODES * D_IN];    // fp16 mean-agg for layer 1
__device__ __half g_agg2h [N_NODES * D_HID];   // fp16 mean-agg for layer 2
__device__ __half g_B1h[128 * 128];            // [K][N] hi(W1) fp16
__device__ __half g_B1l[128 * 128];            // lo(W1)
__device__ __half g_B2h[256 * 64];             // [K][N] hi(W2)
__device__ __half g_B2l[256 * 64];             // lo(W2)

// ===========================================================================
// CSR build
// ===========================================================================
__global__ void zero_int_kernel(int4* __restrict__ p, int n4) {
    int i = blockIdx.x * blockDim.x + threadIdx.x;
    if (i < n4) p[i] = make_int4(0, 0, 0, 0);
}

__global__ void count_kernel(const int2* __restrict__ dst2, int* __restrict__ cnt, int E2) {
    int e = blockIdx.x * blockDim.x + threadIdx.x;
    if (e < E2) {
        int2 d = dst2[e];
        atomicAdd(&cnt[d.x], 1);
        atomicAdd(&cnt[d.y], 1);
    }
}

// Phase 1: per-tile exclusive scan (coalesced), tile totals to bsum.
__global__ __launch_bounds__(SCAN_TILE)
void scan_local_kernel(const int* __restrict__ cnt,
                       int* __restrict__ local,
                       int* __restrict__ bsum, int n) {
    __shared__ int s[SCAN_TILE];
    const int tid = threadIdx.x;
    const int gid = blockIdx.x * SCAN_TILE + tid;
    int v = (gid < n) ? cnt[gid] : 0;
    s[tid] = v;
    __syncthreads();
    for (int off = 1; off < SCAN_TILE; off <<= 1) {
        int t = 0;
        if (tid >= off) t = s[tid - off];
        __syncthreads();
        if (tid >= off) s[tid] += t;
        __syncthreads();
    }
    if (gid < n) local[gid] = s[tid] - v;          // exclusive within tile
    if (tid == SCAN_TILE - 1) bsum[blockIdx.x] = s[tid];
}

// Phase 2: single small block scans the tile totals (exclusive, in place).
__global__ __launch_bounds__(128)
void scan_sums_kernel(int* __restrict__ bsum, int nB) {
    __shared__ int s[128];
    const int tid = threadIdx.x;
    int v = (tid < nB) ? bsum[tid] : 0;
    s[tid] = v;
    __syncthreads();
    for (int off = 1; off < 128; off <<= 1) {
        int t = 0;
        if (tid >= off) t = s[tid - off];
        __syncthreads();
        if (tid >= off) s[tid] += t;
        __syncthreads();
    }
    if (tid < nB) bsum[tid] = s[tid] - v;          // exclusive offsets
}

// Phase 3: add tile offsets; emit row_ptr + cursor; row_ptr[n] = E.
__global__ void scan_add_kernel(const int* __restrict__ bsum,
                                int* __restrict__ row_ptr,
                                int* __restrict__ cursor, int n, int E) {
    int gid = blockIdx.x * blockDim.x + threadIdx.x;
    if (gid < n) {
        int v = row_ptr[gid] + bsum[gid / SCAN_TILE];
        row_ptr[gid] = v;
        cursor[gid] = v;
    }
    if (gid == 0) row_ptr[n] = E;
}

__global__ void fill_kernel(const int2* __restrict__ src2,
                            const int2* __restrict__ dst2,
                            int* __restrict__ cursor,
                            int* __restrict__ csr, int E2) {
    int e = blockIdx.x * blockDim.x + threadIdx.x;
    if (e < E2) {
        int2 s = src2[e];
        int2 d = dst2[e];
        int p0 = atomicAdd(&cursor[d.x], 1);
        csr[p0] = s.x;
        int p1 = atomicAdd(&cursor[d.y], 1);
        csr[p1] = s.y;
    }
}

// fp32 -> fp16 mirror
__global__ void f2h_kernel(const float4* __restrict__ in,
                           __half2* __restrict__ out, int n4) {
    int i = blockIdx.x * blockDim.x + threadIdx.x;
    if (i >= n4) return;
    float4 v = in[i];
    out[i * 2]     = __floats2half2_rn(v.x, v.y);
    out[i * 2 + 1] = __floats2half2_rn(v.z, v.w);
}

// ===========================================================================
// Gather + mean over fp16 features. Edge pairs summed via HADD2, accumulated
// fp32. TPN threads per node; one LDG.128 per thread per edge.
// ===========================================================================
template <int TPN>
__global__ __launch_bounds__(256)
void gather_h_kernel(const uint4* __restrict__ feat,
                     const int* __restrict__ csr,
                     const int* __restrict__ row_ptr,
                     uint4* __restrict__ aggmean_h, int n) {
    const int tid = threadIdx.x;
    const int node = blockIdx.x * (256 / TPN) + tid / TPN;
    const int c = tid % TPN;
    if (node >= n) return;
    const int b = row_ptr[node];
    const int e = row_ptr[node + 1];
    float acc[8];
#pragma unroll
    for (int q = 0; q < 8; q++) acc[q] = 0.f;

    int i = b;
#pragma unroll 2
    for (; i + 1 < e; i += 2) {
        int s0 = __ldg(&csr[i]);
        int s1 = __ldg(&csr[i + 1]);
        uint4 r0 = __ldg(&feat[(size_t)s0 * TPN + c]);
        uint4 r1 = __ldg(&feat[(size_t)s1 * TPN + c]);
        const __half2* p0 = reinterpret_cast<const __half2*>(&r0);
        const __half2* p1 = reinterpret_cast<const __half2*>(&r1);
#pragma unroll
        for (int q = 0; q < 4; q++) {
            __half2 hs = __hadd2(p0[q], p1[q]);
            float2 f = __half22float2(hs);
            acc[2 * q]     += f.x;
            acc[2 * q + 1] += f.y;
        }
    }
    if (i < e) {
        int s = __ldg(&csr[i]);
        uint4 r = __ldg(&feat[(size_t)s * TPN + c]);
        const __half2* ph = reinterpret_cast<const __half2*>(&r);
#pragma unroll
        for (int q = 0; q < 4; q++) {
            float2 f = __half22float2(ph[q]);
            acc[2 * q]     += f.x;
            acc[2 * q + 1] += f.y;
        }
    }

    int d = e - b;
    float inv = 1.0f / (float)(d > 1 ? d : 1);
    __half2 h0 = __floats2half2_rn(acc[0] * inv, acc[1] * inv);
    __half2 h1 = __floats2half2_rn(acc[2] * inv, acc[3] * inv);
    __half2 h2 = __floats2half2_rn(acc[4] * inv, acc[5] * inv);
    __half2 h3 = __floats2half2_rn(acc[6] * inv, acc[7] * inv);
    aggmean_h[(size_t)node * TPN + c] = make_uint4(
        *(uint32_t*)&h0, *(uint32_t*)&h1, *(uint32_t*)&h2, *(uint32_t*)&h3);
}

// ===========================================================================
// Weight prep: W = [Ws; Wn] stacked -> fp16 hi/lo split, row-major [DK2][NOUT]
// ===========================================================================
template <int DK2, int NOUT>
__global__ void wprep_kernel(const float* __restrict__ ws,
                             const float* __restrict__ wn,
                             __half* __restrict__ Bh,
                             __half* __restrict__ Bl) {
    int i = blockIdx.x * blockDim.x + threadIdx.x;
    if (i >= DK2 * NOUT) return;
    int k = i / NOUT, n = i % NOUT;
    float w = (k < DK2 / 2) ? ws[k * NOUT + n] : wn[(k - DK2 / 2) * NOUT + n];
    __half hi = __float2half_rn(w);
    Bh[i] = hi;
    Bl[i] = __float2half_rn(w - __half2float(hi));
}

// ===========================================================================
// Layer via wmma fp16 GEMM with weight hi/lo compensation (R10 form).
// CTA = 128 nodes x NOUT, 8 warps. Warp tile (WROWS*16) x (WCOLS*16).
// LAYER==1: self = xh,  agg = agg1h. Output: fp16 h1h.
// LAYER==2: self = h1h, agg = agg2h. Output: fp32 d_out.
// ===========================================================================
template <int NOUT, int WROWS, int WCOLS, int NCHUNK, int LAYER, bool RELU, bool HALF_OUT>
__global__ __launch_bounds__(256)
void wmma_layer_kernel(const __half* __restrict__ selfh,
                       const __half* __restrict__ aggh,
                       const __half* __restrict__ Bh,
                       const __half* __restrict__ Bl,
                       const float* __restrict__ bias,
                       float* __restrict__ out,
                       __half* __restrict__ outh, int nNodes) {
    constexpr int ROWU4 = (LAYER == 1) ? 8 : 16;  // fp16 source row in uint4
    constexpr int ASTR  = 72;                     // smem A row stride (halfs)
    constexpr int BSTR  = NOUT + 8;               // smem B row stride (halfs)
    constexpr int COLG  = NOUT / (WCOLS * 16);    // warp col groups

    extern __shared__ __align__(32) char smem_raw[];
    __half* sA  = (__half*)smem_raw;                 // 128 x ASTR
    __half* sBh = sA + 128 * ASTR;                   // 64 x BSTR
    __half* sBl = sBh + 64 * BSTR;                   // 64 x BSTR
    float*  sBias = (float*)(sBl + 64 * BSTR);       // 2048 floats

    const int tid = threadIdx.x;
    const int wid = tid >> 5;
    const int lane = tid & 31;
    const int rowg = wid / COLG;
    const int colg = wid % COLG;
    const int base = blockIdx.x * 128;

    for (int i = tid; i < 16 * NOUT; i += 256) sBias[i] = bias[i % NOUT];
    __syncthreads();

    wmma::fragment<wmma::accumulator, 16, 16, 16, float> acc[WROWS][WCOLS];
#pragma unroll
    for (int r = 0; r < WROWS; r++)
#pragma unroll
        for (int c = 0; c < WCOLS; c++)
            wmma::load_matrix_sync(acc[r][c],
                sBias + (colg * WCOLS + c) * 16, NOUT, wmma::mem_row_major);

    for (int kc = 0; kc < NCHUNK; kc++) {
        __syncthreads();

        // ---- stage A: straight fp16 copy, 128 rows x 64 cols ----
        const uint4* src4;
        int qoff;
        if (LAYER == 1) {
            src4 = reinterpret_cast<const uint4*>(kc ? aggh : selfh);
            qoff = 0;
        } else {
            src4 = reinterpret_cast<const uint4*>((kc < 2) ? selfh : aggh);
            qoff = (kc & 1) * 8;
        }
#pragma unroll
        for (int jj = tid; jj < 1024; jj += 256) {
            int m = jj >> 3, c8 = jj & 7;
            int node = base + m;
            uint4 v = make_uint4(0, 0, 0, 0);
            if (node < nNodes)
                v = src4[(size_t)node * ROWU4 + qoff + c8];
            *reinterpret_cast<uint4*>(&sA[m * ASTR + c8 * 8]) = v;
        }
        // ---- stage B: 64 x NOUT fp16 hi/lo ----
#pragma unroll
        for (int jj = tid; jj < 64 * NOUT / 8; jj += 256) {
            int r = jj / (NOUT / 8), c8 = jj % (NOUT / 8);
            size_t g = (size_t)(kc * 64 + r) * NOUT + c8 * 8;
            *reinterpret_cast<uint4*>(&sBh[r * BSTR + c8 * 8]) =
                *reinterpret_cast<const uint4*>(&Bh[g]);
            *reinterpret_cast<uint4*>(&sBl[r * BSTR + c8 * 8]) =
                *reinterpret_cast<const uint4*>(&Bl[g]);
        }
        __syncthreads();

        // ---- MMA over 4 k-steps of 16 ----
#pragma unroll
        for (int kk = 0; kk < 4; kk++) {
            wmma::fragment<wmma::matrix_a, 16, 16, 16, __half, wmma::row_major> a[WROWS];
#pragma unroll
            for (int r = 0; r < WROWS; r++) {
                int rr = (rowg * WROWS + r) * 16;
                wmma::load_matrix_sync(a[r], sA + rr * ASTR + kk * 16, ASTR);
            }
#pragma unroll
            for (int c = 0; c < WCOLS; c++) {
                wmma::fragment<wmma::matrix_b, 16, 16, 16, __half, wmma::row_major> bh, bl;
                int cc = (colg * WCOLS + c) * 16;
                wmma::load_matrix_sync(bh, sBh + kk * 16 * BSTR + cc, BSTR);
                wmma::load_matrix_sync(bl, sBl + kk * 16 * BSTR + cc, BSTR);
#pragma unroll
                for (int r = 0; r < WROWS; r++) {
                    wmma::mma_sync(acc[r][c], a[r], bh, acc[r][c]);
                    wmma::mma_sync(acc[r][c], a[r], bl, acc[r][c]);
                }
            }
        }
    }

    // ---- epilogue ----
    float* scratch = sBias + wid * 256;   // per-warp 16x16 fp32 tile
#pragma unroll
    for (int r = 0; r < WROWS; r++) {
        int rbase = base + (rowg * WROWS + r) * 16;
        if (rbase < nNodes) {
#pragma unroll
            for (int c = 0; c < WCOLS; c++) {
                if (RELU) {
#pragma unroll
                    for (int i = 0; i < acc[r][c].num_elements; i++)
                        acc[r][c].x[i] = fmaxf(acc[r][c].x[i], 0.f);
                }
                int cc = (colg * WCOLS + c) * 16;
                if (HALF_OUT) {
                    __syncwarp();
                    wmma::store_matrix_sync(scratch, acc[r][c], 16,
                                            wmma::mem_row_major);
                    __syncwarp();
                    int lr = lane >> 1, lc = (lane & 1) * 8;
                    float4 va = *reinterpret_cast<float4*>(&scratch[lr * 16 + lc]);
                    float4 vb = *reinterpret_cast<float4*>(&scratch[lr * 16 + lc + 4]);
                    __half2 h0 = __floats2half2_rn(va.x, va.y);
                    __half2 h1 = __floats2half2_rn(va.z, va.w);
                    __half2 h2 = __floats2half2_rn(vb.x, vb.y);
                    __half2 h3 = __floats2half2_rn(vb.z, vb.w);
                    uint4 packed = make_uint4(
                        *(uint32_t*)&h0, *(uint32_t*)&h1,
                        *(uint32_t*)&h2, *(uint32_t*)&h3);
                    *reinterpret_cast<uint4*>(
                        &outh[(size_t)(rbase + lr) * NOUT + cc + lc]) = packed;
                } else {
                    wmma::store_matrix_sync(
                        out + (size_t)rbase * NOUT + cc,
                        acc[r][c], NOUT, wmma::mem_row_major);
                }
            }
        }
    }
}

// ===========================================================================
extern "C" void kernel_launch(void* const* d_in, const int* in_sizes, int n_in,
                              void* d_out, int out_size) {
    const float* x        = (const float*)d_in[0];
    const int*   src      = (const int*)d_in[1];
    const int*   dst      = (const int*)d_in[2];
    const float* w_self1  = (const float*)d_in[3];
    const float* w_neigh1 = (const float*)d_in[4];
    const float* b1       = (const float*)d_in[5];
    const float* w_self2  = (const float*)d_in[6];
    const float* w_neigh2 = (const float*)d_in[7];
    const float* b2       = (const float*)d_in[8];
    float* out = (float*)d_out;

    const int E = in_sizes[1];

    int *cnt, *rowptr, *cursor, *bsum, *csrsrc;
    __half *xh, *h1h, *agg1h, *agg2h;
    __half *B1h, *B1l, *B2h, *B2l;
    cudaGetSymbolAddress((void**)&cnt,    g_cnt);
    cudaGetSymbolAddress((void**)&rowptr, g_rowptr);
    cudaGetSymbolAddress((void**)&cursor, g_cursor);
    cudaGetSymbolAddress((void**)&bsum,   g_bsum);
    cudaGetSymbolAddress((void**)&csrsrc, g_csrsrc);
    cudaGetSymbolAddress((void**)&xh,     g_xh);
    cudaGetSymbolAddress((void**)&h1h,    g_h1h);
    cudaGetSymbolAddress((void**)&agg1h,  g_agg1h);
    cudaGetSymbolAddress((void**)&agg2h,  g_agg2h);
    cudaGetSymbolAddress((void**)&B1h,    g_B1h);
    cudaGetSymbolAddress((void**)&B1l,    g_B1l);
    cudaGetSymbolAddress((void**)&B2h,    g_B2h);
    cudaGetSymbolAddress((void**)&B2l,    g_B2l);

    // smem: A (128x72 half) + B hi/lo (2 x 64 x (NOUT+8) half) + 2048 floats
    constexpr int SMEM_L1 = 128 * 72 * 2 + 2 * 64 * (128 + 8) * 2 + 2048 * 4; // 61440
    constexpr int SMEM_L2 = 128 * 72 * 2 + 2 * 64 * (64 + 8) * 2 + 2048 * 4;  // 45056
    cudaFuncSetAttribute((const void*)wmma_layer_kernel<D_HID, 2, 4, 2, 1, true, true>,
                         cudaFuncAttributeMaxDynamicSharedMemorySize, SMEM_L1);
    cudaFuncSetAttribute((const void*)wmma_layer_kernel<D_OUT, 1, 4, 4, 2, false, false>,
                         cudaFuncAttributeMaxDynamicSharedMemorySize, SMEM_L2);

    const int nTiles = (N_NODES + 127) / 128;
    const int E2 = E / 2;   // E is even (1e6)

    // launch 1: f2h (independent)
    f2h_kernel<<<(N_NODES * D_IN / 4 + 255) / 256, 256>>>(
        (const float4*)x, (__half2*)xh, N_NODES * D_IN / 4);

    // --- CSR build: count + 3-phase parallel scan + fill ---
    zero_int_kernel<<<(N_NODES / 4 + 255) / 256, 256>>>((int4*)cnt, N_NODES / 4);
    count_kernel<<<(E2 + 255) / 256, 256>>>((const int2*)dst, cnt, E2);
    scan_local_kernel<<<N_TILES, SCAN_TILE>>>(cnt, rowptr, bsum, N_NODES);  // slot 4
    scan_sums_kernel<<<1, 128>>>(bsum, N_TILES);
    scan_add_kernel<<<(N_NODES + 255) / 256, 256>>>(bsum, rowptr, cursor, N_NODES, E);
    fill_kernel<<<(E2 + 255) / 256, 256>>>(
        (const int2*)src, (const int2*)dst, cursor, csrsrc, E2);

    // --- weight prep ---
    wprep_kernel<128, 128><<<(128 * 128 + 255) / 256, 256>>>(w_self1, w_neigh1, B1h, B1l);
    wprep_kernel<256, 64><<<(256 * 64 + 255) / 256, 256>>>(w_self2, w_neigh2, B2h, B2l);

    // --- Layer 1 ---
    gather_h_kernel<D_IN / 8><<<(N_NODES * (D_IN / 8) + 255) / 256, 256>>>(
        (const uint4*)xh, csrsrc, rowptr, (uint4*)agg1h, N_NODES);
    wmma_layer_kernel<D_HID, 2, 4, 2, 1, true, true><<<nTiles, 256, SMEM_L1>>>(
        xh, agg1h, B1h, B1l, b1, nullptr, h1h, N_NODES);

    // --- Layer 2 ---
    gather_h_kernel<D_HID / 8><<<(N_NODES * (D_HID / 8) + 255) / 256, 256>>>(
        (const uint4*)h1h, csrsrc, rowptr, (uint4*)agg2h, N_NODES);
    wmma_layer_kernel<D_OUT, 1, 4, 4, 2, false, false><<<nTiles, 256, SMEM_L2>>>(
        h1h, agg2h, B2h, B2l, b2, out, nullptr, N_NODES);
}

// round 14
// speedup vs baseline: 2.1819x; 1.0417x over previous
#include <cuda_runtime.h>
#include <cuda_fp16.h>
#include <mma.h>
#include <cstdint>

using namespace nvcuda;

// ---------------------------------------------------------------------------
// GraphSAGE 2-layer forward, fp16 datapath:
//   CSR build: count(+position record) -> 3-phase parallel scan -> atomic-free
//   fill. HADD2 pair-accumulating gathers; wmma fp16 GEMM with fp32
//   accumulate + fp16 weight split (W = Wh + Wl). Small kernels merged.
// N = 100000, E = 1e6, d_in=64, d_hid=128, d_out=64.
// ---------------------------------------------------------------------------

#define N_NODES 100000
#define E_MAX   1000000
#define D_IN    64
#define D_HID   128
#define D_OUT   64
#define SCAN_TILE 1024
#define N_TILES ((N_NODES + SCAN_TILE - 1) / SCAN_TILE)   // 98

// Scratch (device globals; no allocation allowed)
__device__ int    g_cnt   [N_NODES];
__device__ int    g_rowptr[N_NODES + 1];
__device__ int    g_bsum  [128];
__device__ int    g_pos   [E_MAX];             // per-edge within-bucket slot
__device__ int    g_csrsrc[E_MAX];
__device__ __half g_xh    [N_NODES * D_IN];    // fp16 mirror of x
__device__ __half g_h1h   [N_NODES * D_HID];   // fp16 h1 (sole copy)
__device__ __half g_agg1h [N_NODES * D_IN];    // fp16 mean-agg for layer 1
__device__ __half g_agg2h [N_NODES * D_HID];   // fp16 mean-agg for layer 2
__device__ __half g_B1h[128 * 128];            // [K][N] hi(W1) fp16
__device__ __half g_B1l[128 * 128];            // lo(W1)
__device__ __half g_B2h[256 * 64];             // [K][N] hi(W2)
__device__ __half g_B2l[256 * 64];             // lo(W2)

// ===========================================================================
// prep: fp32->fp16 mirror of x  +  zero the count array (one launch)
// ===========================================================================
#define F2H_N4   (N_NODES * D_IN / 4)          // 1.6M floats -> 400k float4
#define ZERO_N4  (N_NODES / 4)                 // 25k int4
__global__ void prep_kernel(const float4* __restrict__ x4,
                            __half2* __restrict__ xh2,
                            int4* __restrict__ cnt4) {
    int i = blockIdx.x * blockDim.x + threadIdx.x;
    if (i < F2H_N4) {
        float4 v = x4[i];
        xh2[i * 2]     = __floats2half2_rn(v.x, v.y);
        xh2[i * 2 + 1] = __floats2half2_rn(v.z, v.w);
    }
    if (i < ZERO_N4) cnt4[i] = make_int4(0, 0, 0, 0);
}

// count + per-edge position record
__global__ void count_kernel(const int2* __restrict__ dst2,
                             int* __restrict__ cnt,
                             int2* __restrict__ pos2, int E2) {
    int e = blockIdx.x * blockDim.x + threadIdx.x;
    if (e < E2) {
        int2 d = dst2[e];
        int p0 = atomicAdd(&cnt[d.x], 1);
        int p1 = atomicAdd(&cnt[d.y], 1);
        pos2[e] = make_int2(p0, p1);
    }
}

// Phase 1: per-tile exclusive scan (coalesced), tile totals to bsum.
__global__ __launch_bounds__(SCAN_TILE)
void scan_local_kernel(const int* __restrict__ cnt,
                       int* __restrict__ local,
                       int* __restrict__ bsum, int n) {
    __shared__ int s[SCAN_TILE];
    const int tid = threadIdx.x;
    const int gid = blockIdx.x * SCAN_TILE + tid;
    int v = (gid < n) ? cnt[gid] : 0;
    s[tid] = v;
    __syncthreads();
    for (int off = 1; off < SCAN_TILE; off <<= 1) {
        int t = 0;
        if (tid >= off) t = s[tid - off];
        __syncthreads();
        if (tid >= off) s[tid] += t;
        __syncthreads();
    }
    if (gid < n) local[gid] = s[tid] - v;          // exclusive within tile
    if (tid == SCAN_TILE - 1) bsum[blockIdx.x] = s[tid];
}

// Phase 2: single small block scans the tile totals (exclusive, in place).
__global__ __launch_bounds__(128)
void scan_sums_kernel(int* __restrict__ bsum, int nB) {
    __shared__ int s[128];
    const int tid = threadIdx.x;
    int v = (tid < nB) ? bsum[tid] : 0;
    s[tid] = v;
    __syncthreads();
    for (int off = 1; off < 128; off <<= 1) {
        int t = 0;
        if (tid >= off) t = s[tid - off];
        __syncthreads();
        if (tid >= off) s[tid] += t;
        __syncthreads();
    }
    if (tid < nB) bsum[tid] = s[tid] - v;          // exclusive offsets
}

// Phase 3: add tile offsets; finalize row_ptr; row_ptr[n] = E.
__global__ void scan_add_kernel(const int* __restrict__ bsum,
                                int* __restrict__ row_ptr, int n, int E) {
    int gid = blockIdx.x * blockDim.x + threadIdx.x;
    if (gid < n) row_ptr[gid] += bsum[gid / SCAN_TILE];
    if (gid == 0) row_ptr[n] = E;
}

// Atomic-free fill: slot comes from the recorded per-edge position.
__global__ void fill_kernel(const int2* __restrict__ src2,
                            const int2* __restrict__ dst2,
                            const int2* __restrict__ pos2,
                            const int* __restrict__ row_ptr,
                            int* __restrict__ csr, int E2) {
    int e = blockIdx.x * blockDim.x + threadIdx.x;
    if (e < E2) {
        int2 s = src2[e];
        int2 d = dst2[e];
        int2 p = pos2[e];
        csr[row_ptr[d.x] + p.x] = s.x;
        csr[row_ptr[d.y] + p.y] = s.y;
    }
}

// ===========================================================================
// Gather + mean over fp16 features (trailing blocks run weight prep).
// Edge pairs summed via HADD2, accumulated fp32. TPN threads per node.
// ===========================================================================
__device__ __forceinline__ void wprep_item(const float* ws, const float* wn,
                                           __half* Bh, __half* Bl,
                                           int DK2, int NOUT, int i) {
    int k = i / NOUT, n = i % NOUT;
    float w = (k < DK2 / 2) ? ws[k * NOUT + n] : wn[(k - DK2 / 2) * NOUT + n];
    __half hi = __float2half_rn(w);
    Bh[i] = hi;
    Bl[i] = __float2half_rn(w - __half2float(hi));
}

template <int TPN, bool WPREP>
__global__ __launch_bounds__(256)
void gather_h_kernel(const uint4* __restrict__ feat,
                     const int* __restrict__ csr,
                     const int* __restrict__ row_ptr,
                     uint4* __restrict__ aggmean_h, int n,
                     int nGatherBlocks,
                     const float* __restrict__ ws1, const float* __restrict__ wn1,
                     __half* __restrict__ B1h, __half* __restrict__ B1l,
                     const float* __restrict__ ws2, const float* __restrict__ wn2,
                     __half* __restrict__ B2h, __half* __restrict__ B2l) {
    const int tid = threadIdx.x;
    if (WPREP && blockIdx.x >= nGatherBlocks) {
        // trailing blocks: weight prep (layer1: 16384 items, layer2: 16384)
        int b = blockIdx.x - nGatherBlocks;
        int i = b * 256 + tid;
        if (i < 128 * 128) wprep_item(ws1, wn1, B1h, B1l, 128, 128, i);
        int j = i;  // same index range for layer2: 256*64 = 16384
        if (j < 256 * 64) wprep_item(ws2, wn2, B2h, B2l, 256, 64, j);
        return;
    }
    const int node = blockIdx.x * (256 / TPN) + tid / TPN;
    const int c = tid % TPN;
    if (node >= n) return;
    const int b = row_ptr[node];
    const int e = row_ptr[node + 1];
    float acc[8];
#pragma unroll
    for (int q = 0; q < 8; q++) acc[q] = 0.f;

    int i = b;
#pragma unroll 2
    for (; i + 1 < e; i += 2) {
        int s0 = __ldg(&csr[i]);
        int s1 = __ldg(&csr[i + 1]);
        uint4 r0 = __ldg(&feat[(size_t)s0 * TPN + c]);
        uint4 r1 = __ldg(&feat[(size_t)s1 * TPN + c]);
        const __half2* p0 = reinterpret_cast<const __half2*>(&r0);
        const __half2* p1 = reinterpret_cast<const __half2*>(&r1);
#pragma unroll
        for (int q = 0; q < 4; q++) {
            __half2 hs = __hadd2(p0[q], p1[q]);
            float2 f = __half22float2(hs);
            acc[2 * q]     += f.x;
            acc[2 * q + 1] += f.y;
        }
    }
    if (i < e) {
        int s = __ldg(&csr[i]);
        uint4 r = __ldg(&feat[(size_t)s * TPN + c]);
        const __half2* ph = reinterpret_cast<const __half2*>(&r);
#pragma unroll
        for (int q = 0; q < 4; q++) {
            float2 f = __half22float2(ph[q]);
            acc[2 * q]     += f.x;
            acc[2 * q + 1] += f.y;
        }
    }

    int d = e - b;
    float inv = 1.0f / (float)(d > 1 ? d : 1);
    __half2 h0 = __floats2half2_rn(acc[0] * inv, acc[1] * inv);
    __half2 h1 = __floats2half2_rn(acc[2] * inv, acc[3] * inv);
    __half2 h2 = __floats2half2_rn(acc[4] * inv, acc[5] * inv);
    __half2 h3 = __floats2half2_rn(acc[6] * inv, acc[7] * inv);
    aggmean_h[(size_t)node * TPN + c] = make_uint4(
        *(uint32_t*)&h0, *(uint32_t*)&h1, *(uint32_t*)&h2, *(uint32_t*)&h3);
}

// ===========================================================================
// Layer via wmma fp16 GEMM with weight hi/lo compensation.
// CTA = 128 nodes x NOUT, 8 warps. Warp tile (WROWS*16) x (WCOLS*16).
// LAYER==1: self = xh,  agg = agg1h. Output: fp16 h1h.
// LAYER==2: self = h1h, agg = agg2h. Output: fp32 d_out.
// ===========================================================================
template <int NOUT, int WROWS, int WCOLS, int NCHUNK, int LAYER, bool RELU, bool HALF_OUT>
__global__ __launch_bounds__(256)
void wmma_layer_kernel(const __half* __restrict__ selfh,
                       const __half* __restrict__ aggh,
                       const __half* __restrict__ Bh,
                       const __half* __restrict__ Bl,
                       const float* __restrict__ bias,
                       float* __restrict__ out,
                       __half* __restrict__ outh, int nNodes) {
    constexpr int ROWU4 = (LAYER == 1) ? 8 : 16;  // fp16 source row in uint4
    constexpr int ASTR  = 72;                     // smem A row stride (halfs)
    constexpr int BSTR  = NOUT + 8;               // smem B row stride (halfs)
    constexpr int COLG  = NOUT / (WCOLS * 16);    // warp col groups

    extern __shared__ __align__(32) char smem_raw[];
    __half* sA  = (__half*)smem_raw;                 // 128 x ASTR
    __half* sBh = sA + 128 * ASTR;                   // 64 x BSTR
    __half* sBl = sBh + 64 * BSTR;                   // 64 x BSTR
    float*  sBias = (float*)(sBl + 64 * BSTR);       // 2048 floats

    const int tid = threadIdx.x;
    const int wid = tid >> 5;
    const int lane = tid & 31;
    const int rowg = wid / COLG;
    const int colg = wid % COLG;
    const int base = blockIdx.x * 128;

    for (int i = tid; i < 16 * NOUT; i += 256) sBias[i] = bias[i % NOUT];
    __syncthreads();

    wmma::fragment<wmma::accumulator, 16, 16, 16, float> acc[WROWS][WCOLS];
#pragma unroll
    for (int r = 0; r < WROWS; r++)
#pragma unroll
        for (int c = 0; c < WCOLS; c++)
            wmma::load_matrix_sync(acc[r][c],
                sBias + (colg * WCOLS + c) * 16, NOUT, wmma::mem_row_major);

    for (int kc = 0; kc < NCHUNK; kc++) {
        __syncthreads();

        // ---- stage A: straight fp16 copy, 128 rows x 64 cols ----
        const uint4* src4;
        int qoff;
        if (LAYER == 1) {
            src4 = reinterpret_cast<const uint4*>(kc ? aggh : selfh);
            qoff = 0;
        } else {
            src4 = reinterpret_cast<const uint4*>((kc < 2) ? selfh : aggh);
            qoff = (kc & 1) * 8;
        }
#pragma unroll
        for (int jj = tid; jj < 1024; jj += 256) {
            int m = jj >> 3, c8 = jj & 7;
            int node = base + m;
            uint4 v = make_uint4(0, 0, 0, 0);
            if (node < nNodes)
                v = src4[(size_t)node * ROWU4 + qoff + c8];
            *reinterpret_cast<uint4*>(&sA[m * ASTR + c8 * 8]) = v;
        }
        // ---- stage B: 64 x NOUT fp16 hi/lo ----
#pragma unroll
        for (int jj = tid; jj < 64 * NOUT / 8; jj += 256) {
            int r = jj / (NOUT / 8), c8 = jj % (NOUT / 8);
            size_t g = (size_t)(kc * 64 + r) * NOUT + c8 * 8;
            *reinterpret_cast<uint4*>(&sBh[r * BSTR + c8 * 8]) =
                *reinterpret_cast<const uint4*>(&Bh[g]);
            *reinterpret_cast<uint4*>(&sBl[r * BSTR + c8 * 8]) =
                *reinterpret_cast<const uint4*>(&Bl[g]);
        }
        __syncthreads();

        // ---- MMA over 4 k-steps of 16 ----
#pragma unroll
        for (int kk = 0; kk < 4; kk++) {
            wmma::fragment<wmma::matrix_a, 16, 16, 16, __half, wmma::row_major> a[WROWS];
#pragma unroll
            for (int r = 0; r < WROWS; r++) {
                int rr = (rowg * WROWS + r) * 16;
                wmma::load_matrix_sync(a[r], sA + rr * ASTR + kk * 16, ASTR);
            }
#pragma unroll
            for (int c = 0; c < WCOLS; c++) {
                wmma::fragment<wmma::matrix_b, 16, 16, 16, __half, wmma::row_major> bh, bl;
                int cc = (colg * WCOLS + c) * 16;
                wmma::load_matrix_sync(bh, sBh + kk * 16 * BSTR + cc, BSTR);
                wmma::load_matrix_sync(bl, sBl + kk * 16 * BSTR + cc, BSTR);
#pragma unroll
                for (int r = 0; r < WROWS; r++) {
                    wmma::mma_sync(acc[r][c], a[r], bh, acc[r][c]);
                    wmma::mma_sync(acc[r][c], a[r], bl, acc[r][c]);
                }
            }
        }
    }

    // ---- epilogue ----
    float* scratch = sBias + wid * 256;   // per-warp 16x16 fp32 tile
#pragma unroll
    for (int r = 0; r < WROWS; r++) {
        int rbase = base + (rowg * WROWS + r) * 16;
        if (rbase < nNodes) {
#pragma unroll
            for (int c = 0; c < WCOLS; c++) {
                if (RELU) {
#pragma unroll
                    for (int i = 0; i < acc[r][c].num_elements; i++)
                        acc[r][c].x[i] = fmaxf(acc[r][c].x[i], 0.f);
                }
                int cc = (colg * WCOLS + c) * 16;
                if (HALF_OUT) {
                    __syncwarp();
                    wmma::store_matrix_sync(scratch, acc[r][c], 16,
                                            wmma::mem_row_major);
                    __syncwarp();
                    int lr = lane >> 1, lc = (lane & 1) * 8;
                    float4 va = *reinterpret_cast<float4*>(&scratch[lr * 16 + lc]);
                    float4 vb = *reinterpret_cast<float4*>(&scratch[lr * 16 + lc + 4]);
                    __half2 h0 = __floats2half2_rn(va.x, va.y);
                    __half2 h1 = __floats2half2_rn(va.z, va.w);
                    __half2 h2 = __floats2half2_rn(vb.x, vb.y);
                    __half2 h3 = __floats2half2_rn(vb.z, vb.w);
                    uint4 packed = make_uint4(
                        *(uint32_t*)&h0, *(uint32_t*)&h1,
                        *(uint32_t*)&h2, *(uint32_t*)&h3);
                    *reinterpret_cast<uint4*>(
                        &outh[(size_t)(rbase + lr) * NOUT + cc + lc]) = packed;
                } else {
                    wmma::store_matrix_sync(
                        out + (size_t)rbase * NOUT + cc,
                        acc[r][c], NOUT, wmma::mem_row_major);
                }
            }
        }
    }
}

// ===========================================================================
extern "C" void kernel_launch(void* const* d_in, const int* in_sizes, int n_in,
                              void* d_out, int out_size) {
    const float* x        = (const float*)d_in[0];
    const int*   src      = (const int*)d_in[1];
    const int*   dst      = (const int*)d_in[2];
    const float* w_self1  = (const float*)d_in[3];
    const float* w_neigh1 = (const float*)d_in[4];
    const float* b1       = (const float*)d_in[5];
    const float* w_self2  = (const float*)d_in[6];
    const float* w_neigh2 = (const float*)d_in[7];
    const float* b2       = (const float*)d_in[8];
    float* out = (float*)d_out;

    const int E = in_sizes[1];

    int *cnt, *rowptr, *bsum, *pos, *csrsrc;
    __half *xh, *h1h, *agg1h, *agg2h;
    __half *B1h, *B1l, *B2h, *B2l;
    cudaGetSymbolAddress((void**)&cnt,    g_cnt);
    cudaGetSymbolAddress((void**)&rowptr, g_rowptr);
    cudaGetSymbolAddress((void**)&bsum,   g_bsum);
    cudaGetSymbolAddress((void**)&pos,    g_pos);
    cudaGetSymbolAddress((void**)&csrsrc, g_csrsrc);
    cudaGetSymbolAddress((void**)&xh,     g_xh);
    cudaGetSymbolAddress((void**)&h1h,    g_h1h);
    cudaGetSymbolAddress((void**)&agg1h,  g_agg1h);
    cudaGetSymbolAddress((void**)&agg2h,  g_agg2h);
    cudaGetSymbolAddress((void**)&B1h,    g_B1h);
    cudaGetSymbolAddress((void**)&B1l,    g_B1l);
    cudaGetSymbolAddress((void**)&B2h,    g_B2h);
    cudaGetSymbolAddress((void**)&B2l,    g_B2l);

    // smem: A (128x72 half) + B hi/lo (2 x 64 x (NOUT+8) half) + 2048 floats
    constexpr int SMEM_L1 = 128 * 72 * 2 + 2 * 64 * (128 + 8) * 2 + 2048 * 4; // 61440
    constexpr int SMEM_L2 = 128 * 72 * 2 + 2 * 64 * (64 + 8) * 2 + 2048 * 4;  // 45056
    cudaFuncSetAttribute((const void*)wmma_layer_kernel<D_HID, 2, 4, 2, 1, true, true>,
                         cudaFuncAttributeMaxDynamicSharedMemorySize, SMEM_L1);
    cudaFuncSetAttribute((const void*)wmma_layer_kernel<D_OUT, 1, 4, 4, 2, false, false>,
                         cudaFuncAttributeMaxDynamicSharedMemorySize, SMEM_L2);

    const int nTiles = (N_NODES + 127) / 128;
    const int E2 = E / 2;   // E is even (1e6)

    // 1) prep: f2h + zero cnt
    prep_kernel<<<(F2H_N4 + 255) / 256, 256>>>(
        (const float4*)x, (__half2*)xh, (int4*)cnt);

    // 2) count (+ per-edge positions)
    count_kernel<<<(E2 + 255) / 256, 256>>>(
        (const int2*)dst, cnt, (int2*)pos, E2);

    // 3-5) parallel 3-phase scan (scan_local stays launch #4 sentinel... #3 now)
    scan_local_kernel<<<N_TILES, SCAN_TILE>>>(cnt, rowptr, bsum, N_NODES);
    scan_sums_kernel<<<1, 128>>>(bsum, N_TILES);
    scan_add_kernel<<<(N_NODES + 255) / 256, 256>>>(bsum, rowptr, N_NODES, E);

    // 6) atomic-free fill
    fill_kernel<<<(E2 + 255) / 256, 256>>>(
        (const int2*)src, (const int2*)dst, (const int2*)pos, rowptr, csrsrc, E2);

    // 7) gather1 + weight prep (trailing 64 blocks)
    {
        const int gb = (N_NODES * (D_IN / 8) + 255) / 256;   // 3125
        const int wb = (128 * 128 + 255) / 256;              // 64 (covers both preps)
        gather_h_kernel<D_IN / 8, true><<<gb + wb, 256>>>(
            (const uint4*)xh, csrsrc, rowptr, (uint4*)agg1h, N_NODES, gb,
            w_self1, w_neigh1, B1h, B1l, w_self2, w_neigh2, B2h, B2l);
    }

    // 8) layer 1
    wmma_layer_kernel<D_HID, 2, 4, 2, 1, true, true><<<nTiles, 256, SMEM_L1>>>(
        xh, agg1h, B1h, B1l, b1, nullptr, h1h, N_NODES);

    // 9) gather 2
    gather_h_kernel<D_HID / 8, false><<<(N_NODES * (D_HID / 8) + 255) / 256, 256>>>(
        (const uint4*)h1h, csrsrc, rowptr, (uint4*)agg2h, N_NODES, 1 << 30,
        nullptr, nullptr, nullptr, nullptr, nullptr, nullptr, nullptr, nullptr);

    // 10) layer 2
    wmma_layer_kernel<D_OUT, 1, 4, 4, 2, false, false><<<nTiles, 256, SMEM_L2>>>(
        h1h, agg2h, B2h, B2l, b2, out, nullptr, N_NODES);
}